// round 12
// baseline (speedup 1.0000x reference)
#include <cuda_runtime.h>
#include <cuda_bf16.h>
#include <cuda_fp8.h>
#include <math.h>
#include <stdint.h>

#define N_SPK 1024
#define N_UTT 20
#define D_EMB 512
#define ROWS (N_SPK * N_UTT)   // 20480
#define RT 160                 // row tiles
#define CT 8                   // col tiles

// ---------------- device scratch ----------------
__device__ __nv_fp8_e4m3 g_en8[(size_t)ROWS * D_EMB];   // normalized embeddings (e4m3)
__device__ __nv_fp8_e4m3 g_cn8[(size_t)N_SPK * D_EMB];  // normalized centroids (e4m3)
__device__ float g_diag[ROWS];
__device__ float g_rows[RT][CT][128];
__device__ float g_part[RT];
__device__ unsigned int g_cnt[RT];
__device__ unsigned int g_cnt2;

// ---------------- helpers ----------------
__device__ __forceinline__ uint32_t smem_u32(const void* p) {
    uint32_t a;
    asm("{ .reg .u64 t; cvta.to.shared.u64 t, %1; cvt.u32.u64 %0, t; }" : "=r"(a) : "l"(p));
    return a;
}
#define SWZ128(b) ((b) ^ (((b) >> 3) & 0x70))

#define CP_ASYNC16(dst, src) \
    asm volatile("cp.async.cg.shared.global [%0], [%1], 16;" :: "r"(dst), "l"(src))
#define CP_COMMIT()  asm volatile("cp.async.commit_group;" ::: "memory")
#define CP_WAIT0()   asm volatile("cp.async.wait_group 0;" ::: "memory")
#define CP_WAIT1()   asm volatile("cp.async.wait_group 1;" ::: "memory")

#define LDSM_X4(r0, r1, r2, r3, addr) \
    asm volatile("ldmatrix.sync.aligned.m8n8.x4.shared.b16 {%0,%1,%2,%3}, [%4];" \
                 : "=r"(r0), "=r"(r1), "=r"(r2), "=r"(r3) : "r"(addr))

// FP8 e4m3 MMA: m16n8k32, fp32 accumulate
#define MMA_FP8(d, a0, a1, a2, a3, b0, b1) \
    asm volatile("mma.sync.aligned.m16n8k32.row.col.f32.e4m3.e4m3.f32 " \
                 "{%0,%1,%2,%3}, {%4,%5,%6,%7}, {%8,%9}, {%0,%1,%2,%3};" \
                 : "+f"((d)[0]), "+f"((d)[1]), "+f"((d)[2]), "+f"((d)[3]) \
                 : "r"(a0), "r"(a1), "r"(a2), "r"(a3), "r"(b0), "r"(b1))

// ---------------- K1: per-speaker prep ----------------
__global__ __launch_bounds__(256) void prep_kernel(const float* __restrict__ emb) {
    __shared__ float se[N_UTT][D_EMB];
    __shared__ float ss[D_EMB];
    __shared__ float red[256];

    int n = blockIdx.x;
    int tid = threadIdx.x;
    const float* E = emb + (size_t)n * N_UTT * D_EMB;

    for (int i = tid; i < N_UTT * D_EMB; i += 256)
        ((float*)se)[i] = E[i];
    __syncthreads();

    for (int d = tid; d < D_EMB; d += 256) {
        float s = 0.f;
#pragma unroll
        for (int m = 0; m < N_UTT; m++) s += se[m][d];
        ss[d] = s;
    }
    __syncthreads();

    float p = 0.f;
    for (int d = tid; d < D_EMB; d += 256) p += ss[d] * ss[d];
    red[tid] = p;
    __syncthreads();
    for (int off = 128; off > 0; off >>= 1) {
        if (tid < off) red[tid] += red[tid + off];
        __syncthreads();
    }
    float snorm = sqrtf(red[0]);
    float cscale = 1.f / fmaxf(snorm, (float)N_UTT * 1e-8f);
    for (int d = tid; d < D_EMB; d += 256)
        g_cn8[(size_t)n * D_EMB + d] = __nv_fp8_e4m3(ss[d] * cscale);

    int wid = tid >> 5, lane = tid & 31;
    for (int m = wid; m < N_UTT; m += 8) {
        float ee = 0.f, cc = 0.f, ec = 0.f;
        for (int d = lane; d < D_EMB; d += 32) {
            float e = se[m][d];
            float c = ss[d] - e;
            ee += e * e;
            cc += c * c;
            ec += e * c;
        }
#pragma unroll
        for (int o = 16; o > 0; o >>= 1) {
            ee += __shfl_down_sync(0xffffffffu, ee, o);
            cc += __shfl_down_sync(0xffffffffu, cc, o);
            ec += __shfl_down_sync(0xffffffffu, ec, o);
        }
        ee = __shfl_sync(0xffffffffu, ee, 0);
        cc = __shfl_sync(0xffffffffu, cc, 0);
        ec = __shfl_sync(0xffffffffu, ec, 0);

        float ne  = sqrtf(ee);
        float ncl = sqrtf(cc) * (1.f / (float)(N_UTT - 1));
        if (lane == 0) {
            float dg = (ec * (1.f / (float)(N_UTT - 1))) /
                       (fmaxf(ne, 1e-8f) * fmaxf(ncl, 1e-8f));
            g_diag[n * N_UTT + m] = dg;
        }
        float esc = 1.f / fmaxf(ne, 1e-8f);
        for (int d = lane; d < D_EMB; d += 32)
            g_en8[(size_t)(n * N_UTT + m) * D_EMB + d] = __nv_fp8_e4m3(se[m][d] * esc);
    }
}

// ---------------- K2: fp8 mma.sync GEMM, 3-stage pipeline, fused loss ----------------
// Chunk = K:128 fp8 = 128 B/row. Tile 128 rows x 128 B = 16 KB. 4 chunks total.
#define TILE_BYTES 16384
#define A_OFF(s) ((s) * TILE_BYTES)      // stages 0..2
#define B_OFF(s) (49152 + (s) * TILE_BYTES)
#define RS_OFF   98304                   // rowsum2[128][4]
#define RED_OFF  (98304 + 2048)          // red[256]
#define SM_TOTAL (98304 + 2048 + 1024)

__global__ __launch_bounds__(256, 2)
void gemm_loss_kernel(const float* __restrict__ wp, const float* __restrict__ bp,
                      float* __restrict__ out) {
    extern __shared__ char smem[];
    uint32_t sbase = smem_u32(smem);
    float* rowsum2 = (float*)(smem + RS_OFF);
    float* red     = (float*)(smem + RED_OFF);
    __shared__ unsigned int s_ord, s_last2;

    int tid = threadIdx.x;
    int wid = tid >> 5, lane = tid & 31;
    int wr = wid >> 2, wc = wid & 3;

    int by = blockIdx.y, bx = blockIdx.x;
    int rowBase = by * 128;
    int colBase = bx * 128;

    const __nv_fp8_e4m3* Ag = g_en8 + (size_t)rowBase * D_EMB;
    const __nv_fp8_e4m3* Bg = g_cn8 + (size_t)colBase * D_EMB;

    // gmem->smem: 128 rows x 128 B per tile; 1024 16B-chunks; 4 per thread
    int ldRow[4], ldG[4];
    uint32_t ldSw[4];
#pragma unroll
    for (int it = 0; it < 4; it++) {
        int id = it * 256 + tid;
        ldRow[it] = id >> 3;               // 0..127
        ldG[it] = id & 7;                  // 16B group within 128B row
        ldSw[it] = SWZ128((uint32_t)(ldRow[it] * 128 + ldG[it] * 16));
    }

    float acc[4][4][4];
#pragma unroll
    for (int mi = 0; mi < 4; mi++)
#pragma unroll
        for (int ni = 0; ni < 4; ni++)
#pragma unroll
            for (int e = 0; e < 4; e++) acc[mi][ni][e] = 0.f;

    // fragment lane addressing (bytes); identical to bf16 byte layout
    int aRow0 = wr * 64 + (lane & 7) + 8 * ((lane >> 3) & 1);
    int aColB = 16 * (lane >> 4);                      // k-half byte offset
    int bRowOff = ((lane >> 4) & 1) * 8 + (lane & 7);
    int bColB = ((lane >> 3) & 1) * 16;

    // ---- prologue: chunks 0,1 -> stages 0,1 ----
#pragma unroll
    for (int pc = 0; pc < 2; pc++) {
        const __nv_fp8_e4m3* An = Ag + pc * 128;
        const __nv_fp8_e4m3* Bn = Bg + pc * 128;
#pragma unroll
        for (int it = 0; it < 4; it++) {
            CP_ASYNC16(sbase + A_OFF(pc) + ldSw[it], An + (size_t)ldRow[it] * D_EMB + ldG[it] * 16);
            CP_ASYNC16(sbase + B_OFF(pc) + ldSw[it], Bn + (size_t)ldRow[it] * D_EMB + ldG[it] * 16);
        }
        CP_COMMIT();
    }

#pragma unroll
    for (int c = 0; c < 4; c++) {
        int st = c % 3;
        if (c < 3) CP_WAIT1(); else CP_WAIT0();
        __syncthreads();

        if (c < 2) {
            int nst = (c + 2) % 3;
            const __nv_fp8_e4m3* An = Ag + (c + 2) * 128;
            const __nv_fp8_e4m3* Bn = Bg + (c + 2) * 128;
#pragma unroll
            for (int it = 0; it < 4; it++) {
                CP_ASYNC16(sbase + A_OFF(nst) + ldSw[it], An + (size_t)ldRow[it] * D_EMB + ldG[it] * 16);
                CP_ASYNC16(sbase + B_OFF(nst) + ldSw[it], Bn + (size_t)ldRow[it] * D_EMB + ldG[it] * 16);
            }
            CP_COMMIT();
        }

        uint32_t aBase = sbase + A_OFF(st);
        uint32_t bBase = sbase + B_OFF(st);
#pragma unroll
        for (int ks = 0; ks < 4; ks++) {               // K step = 32 fp8 = 32 bytes
            uint32_t bfr[4][2];
#pragma unroll
            for (int nh = 0; nh < 2; nh++) {
                uint32_t addr = bBase + SWZ128((uint32_t)((wc * 32 + nh * 16 + bRowOff) * 128 +
                                                          ks * 32 + bColB));
                LDSM_X4(bfr[nh * 2][0], bfr[nh * 2][1], bfr[nh * 2 + 1][0], bfr[nh * 2 + 1][1], addr);
            }
#pragma unroll
            for (int mi = 0; mi < 4; mi++) {
                uint32_t a0, a1, a2, a3;
                uint32_t addr = aBase + SWZ128((uint32_t)((aRow0 + mi * 16) * 128 +
                                                          ks * 32 + aColB));
                LDSM_X4(a0, a1, a2, a3, addr);
#pragma unroll
                for (int ni = 0; ni < 4; ni++)
                    MMA_FP8(acc[mi][ni], a0, a1, a2, a3, bfr[ni][0], bfr[ni][1]);
            }
        }
    }
    __syncthreads();

    // ---- epilogue ----
    float w = *wp, b = *bp;
    float b2 = fmaf(w, 1e-6f, b);

#pragma unroll
    for (int mi = 0; mi < 4; mi++) {
#pragma unroll
        for (int h = 0; h < 2; h++) {
            int rl = wr * 64 + mi * 16 + (lane >> 2) + 8 * h;
            int grow = rowBase + rl;
            int spk = grow / N_UTT;
            float dg = g_diag[grow];
            float s = 0.f;
#pragma unroll
            for (int ni = 0; ni < 4; ni++) {
#pragma unroll
                for (int e = 0; e < 2; e++) {
                    int col = colBase + wc * 32 + ni * 8 + (lane & 3) * 2 + e;
                    float v = acc[mi][ni][h * 2 + e];
                    v = (col == spk) ? dg : v;
                    s += __expf(fmaf(w, v, b2));
                }
            }
            s += __shfl_xor_sync(0xffffffffu, s, 1);
            s += __shfl_xor_sync(0xffffffffu, s, 2);
            if ((lane & 3) == 0) rowsum2[rl * 4 + wc] = s;
        }
    }
    __syncthreads();

    if (tid < 128) {
        float v = rowsum2[tid * 4 + 0] + rowsum2[tid * 4 + 1] +
                  rowsum2[tid * 4 + 2] + rowsum2[tid * 4 + 3];
        g_rows[by][bx][tid] = v;
    }
    __threadfence();
    __syncthreads();
    if (tid == 0) s_ord = atomicAdd(&g_cnt[by], 1u);
    __syncthreads();

    if (s_ord == CT - 1) {
        float v = 0.f;
        if (tid < 128) {
            float es = 0.f;
#pragma unroll
            for (int x = 0; x < CT; x++) es += g_rows[by][x][tid];
            float lse = logf(es + 1e-6f);
            float pos = fmaf(w, g_diag[rowBase + tid] + 1e-6f, b);
            v = lse - pos;
        }
        red[tid] = v;
        __syncthreads();
        for (int off = 128; off > 0; off >>= 1) {
            if (tid < off) red[tid] += red[tid + off];
            __syncthreads();
        }
        if (tid == 0) {
            g_part[by] = red[0];
            g_cnt[by] = 0;
            __threadfence();
            unsigned int o = atomicAdd(&g_cnt2, 1u);
            s_last2 = (o == RT - 1) ? 1u : 0u;
        }
        __syncthreads();

        if (s_last2) {
            float s = (tid < RT) ? g_part[tid] : 0.f;
            red[tid] = s;
            __syncthreads();
            for (int off = 128; off > 0; off >>= 1) {
                if (tid < off) red[tid] += red[tid + off];
                __syncthreads();
            }
            if (tid == 0) {
                out[0] = red[0];
                g_cnt2 = 0;
            }
        }
    }
}

// ---------------- launch ----------------
extern "C" void kernel_launch(void* const* d_in, const int* in_sizes, int n_in,
                              void* d_out, int out_size) {
    const float* emb = (const float*)d_in[0];
    const float* w   = (const float*)d_in[1];
    const float* b   = (const float*)d_in[2];
    float* out = (float*)d_out;

    cudaFuncSetAttribute(gemm_loss_kernel,
                         cudaFuncAttributeMaxDynamicSharedMemorySize, SM_TOTAL);

    prep_kernel<<<N_SPK, 256>>>(emb);
    dim3 g2(CT, RT);   // (8, 160)
    gemm_loss_kernel<<<g2, 256, SM_TOTAL>>>(w, b, out);
}

// round 13
// speedup vs baseline: 1.2637x; 1.2637x over previous
#include <cuda_runtime.h>
#include <cuda_fp16.h>
#include <math.h>
#include <stdint.h>

#define N_SPK 1024
#define N_UTT 20
#define D_EMB 512
#define ROWS (N_SPK * N_UTT)   // 20480
#define RT 160                 // row tiles
#define CT 8                   // col tiles

// ---------------- device scratch ----------------
__device__ __half g_en_h[(size_t)ROWS * D_EMB];   // normalized embeddings (fp16)
__device__ __half g_cn_h[(size_t)N_SPK * D_EMB];  // normalized centroids (fp16)
__device__ float g_diag[ROWS];
__device__ float g_rows[RT][CT][128];
__device__ float g_part[RT];
__device__ unsigned int g_cnt[RT];
__device__ unsigned int g_cnt2;

// ---------------- helpers ----------------
__device__ __forceinline__ uint32_t smem_u32(const void* p) {
    uint32_t a;
    asm("{ .reg .u64 t; cvta.to.shared.u64 t, %1; cvt.u32.u64 %0, t; }" : "=r"(a) : "l"(p));
    return a;
}
#define SWZ128(b) ((b) ^ (((b) >> 3) & 0x70))

#define CP_ASYNC16(dst, src) \
    asm volatile("cp.async.cg.shared.global [%0], [%1], 16;" :: "r"(dst), "l"(src))
#define CP_COMMIT()  asm volatile("cp.async.commit_group;" ::: "memory")
#define CP_WAIT0()   asm volatile("cp.async.wait_group 0;" ::: "memory")
#define CP_WAIT1()   asm volatile("cp.async.wait_group 1;" ::: "memory")

#define LDSM_X4(r0, r1, r2, r3, addr) \
    asm volatile("ldmatrix.sync.aligned.m8n8.x4.shared.b16 {%0,%1,%2,%3}, [%4];" \
                 : "=r"(r0), "=r"(r1), "=r"(r2), "=r"(r3) : "r"(addr))

// fp16 MMA with fp16 accumulators: full-rate legacy path, 2 acc regs
#define MMA_F16(d, a0, a1, a2, a3, b0, b1) \
    asm volatile("mma.sync.aligned.m16n8k16.row.col.f16.f16.f16.f16 " \
                 "{%0,%1}, {%2,%3,%4,%5}, {%6,%7}, {%0,%1};" \
                 : "+r"((d)[0]), "+r"((d)[1]) \
                 : "r"(a0), "r"(a1), "r"(a2), "r"(a3), "r"(b0), "r"(b1))

// ---------------- K1: per-speaker prep ----------------
__global__ __launch_bounds__(256) void prep_kernel(const float* __restrict__ emb) {
    __shared__ float se[N_UTT][D_EMB];
    __shared__ float ss[D_EMB];
    __shared__ float red[256];

    int n = blockIdx.x;
    int tid = threadIdx.x;
    const float* E = emb + (size_t)n * N_UTT * D_EMB;

    for (int i = tid; i < N_UTT * D_EMB; i += 256)
        ((float*)se)[i] = E[i];
    __syncthreads();

    for (int d = tid; d < D_EMB; d += 256) {
        float s = 0.f;
#pragma unroll
        for (int m = 0; m < N_UTT; m++) s += se[m][d];
        ss[d] = s;
    }
    __syncthreads();

    float p = 0.f;
    for (int d = tid; d < D_EMB; d += 256) p += ss[d] * ss[d];
    red[tid] = p;
    __syncthreads();
    for (int off = 128; off > 0; off >>= 1) {
        if (tid < off) red[tid] += red[tid + off];
        __syncthreads();
    }
    float snorm = sqrtf(red[0]);
    float cscale = 1.f / fmaxf(snorm, (float)N_UTT * 1e-8f);
    for (int d = tid; d < D_EMB; d += 256)
        g_cn_h[(size_t)n * D_EMB + d] = __float2half(ss[d] * cscale);

    int wid = tid >> 5, lane = tid & 31;
    for (int m = wid; m < N_UTT; m += 8) {
        float ee = 0.f, cc = 0.f, ec = 0.f;
        for (int d = lane; d < D_EMB; d += 32) {
            float e = se[m][d];
            float c = ss[d] - e;
            ee += e * e;
            cc += c * c;
            ec += e * c;
        }
#pragma unroll
        for (int o = 16; o > 0; o >>= 1) {
            ee += __shfl_down_sync(0xffffffffu, ee, o);
            cc += __shfl_down_sync(0xffffffffu, cc, o);
            ec += __shfl_down_sync(0xffffffffu, ec, o);
        }
        ee = __shfl_sync(0xffffffffu, ee, 0);
        cc = __shfl_sync(0xffffffffu, cc, 0);
        ec = __shfl_sync(0xffffffffu, ec, 0);

        float ne  = sqrtf(ee);
        float ncl = sqrtf(cc) * (1.f / (float)(N_UTT - 1));
        if (lane == 0) {
            float dg = (ec * (1.f / (float)(N_UTT - 1))) /
                       (fmaxf(ne, 1e-8f) * fmaxf(ncl, 1e-8f));
            g_diag[n * N_UTT + m] = dg;
        }
        float esc = 1.f / fmaxf(ne, 1e-8f);
        for (int d = lane; d < D_EMB; d += 32)
            g_en_h[(size_t)(n * N_UTT + m) * D_EMB + d] = __float2half(se[m][d] * esc);
    }
}

// ---------------- K2: fp16 mma.sync GEMM (f16 acc), 3-stage pipeline, fused loss ----------------
#define TILE_BYTES 16384                 // 128 rows x 64 fp16
#define A_OFF(s) ((s) * TILE_BYTES)      // stages 0..2
#define B_OFF(s) (49152 + (s) * TILE_BYTES)
#define RS_OFF   98304                   // rowsum2[128][4]
#define RED_OFF  (98304 + 2048)          // red[256]
#define SM_TOTAL (98304 + 2048 + 1024)

__global__ __launch_bounds__(256, 2)
void gemm_loss_kernel(const float* __restrict__ wp, const float* __restrict__ bp,
                      float* __restrict__ out) {
    extern __shared__ char smem[];
    uint32_t sbase = smem_u32(smem);
    float* rowsum2 = (float*)(smem + RS_OFF);
    float* red     = (float*)(smem + RED_OFF);
    __shared__ unsigned int s_ord, s_last2;

    int tid = threadIdx.x;
    int wid = tid >> 5, lane = tid & 31;
    int wr = wid >> 2, wc = wid & 3;

    int by = blockIdx.y, bx = blockIdx.x;
    int rowBase = by * 128;
    int colBase = bx * 128;

    const __half* Ag = g_en_h + (size_t)rowBase * D_EMB;
    const __half* Bg = g_cn_h + (size_t)colBase * D_EMB;

    int ldRow[4], ldG[4];
    uint32_t ldSw[4];
#pragma unroll
    for (int it = 0; it < 4; it++) {
        int id = it * 256 + tid;
        ldRow[it] = id >> 3;
        ldG[it] = id & 7;
        ldSw[it] = SWZ128((uint32_t)(ldRow[it] * 128 + ldG[it] * 16));
    }

    uint32_t acc[4][4][2];                 // f16x2 accumulators
#pragma unroll
    for (int mi = 0; mi < 4; mi++)
#pragma unroll
        for (int ni = 0; ni < 4; ni++) {
            acc[mi][ni][0] = 0u;
            acc[mi][ni][1] = 0u;
        }

    int aRow0 = wr * 64 + (lane & 7) + 8 * ((lane >> 3) & 1);
    int aColQ = 8 * (lane >> 4);
    int bRowOff = ((lane >> 4) & 1) * 8 + (lane & 7);
    int bColQ = ((lane >> 3) & 1) * 8;

    // ---- prologue: chunks 0,1 -> stages 0,1 ----
#pragma unroll
    for (int pc = 0; pc < 2; pc++) {
        const __half* An = Ag + pc * 64;
        const __half* Bn = Bg + pc * 64;
#pragma unroll
        for (int it = 0; it < 4; it++) {
            CP_ASYNC16(sbase + A_OFF(pc) + ldSw[it], An + (size_t)ldRow[it] * D_EMB + ldG[it] * 8);
            CP_ASYNC16(sbase + B_OFF(pc) + ldSw[it], Bn + (size_t)ldRow[it] * D_EMB + ldG[it] * 8);
        }
        CP_COMMIT();
    }

#pragma unroll
    for (int c = 0; c < 8; c++) {
        int st = c % 3;
        if (c < 7) CP_WAIT1(); else CP_WAIT0();
        __syncthreads();                   // the ONLY barrier per chunk

        if (c < 6) {
            int nst = (c + 2) % 3;
            const __half* An = Ag + (c + 2) * 64;
            const __half* Bn = Bg + (c + 2) * 64;
#pragma unroll
            for (int it = 0; it < 4; it++) {
                CP_ASYNC16(sbase + A_OFF(nst) + ldSw[it], An + (size_t)ldRow[it] * D_EMB + ldG[it] * 8);
                CP_ASYNC16(sbase + B_OFF(nst) + ldSw[it], Bn + (size_t)ldRow[it] * D_EMB + ldG[it] * 8);
            }
            CP_COMMIT();
        }

        uint32_t aBase = sbase + A_OFF(st);
        uint32_t bBase = sbase + B_OFF(st);
#pragma unroll
        for (int ks = 0; ks < 4; ks++) {
            uint32_t bfr[4][2];
#pragma unroll
            for (int nh = 0; nh < 2; nh++) {
                uint32_t addr = bBase + SWZ128((uint32_t)((wc * 32 + nh * 16 + bRowOff) * 128 +
                                                          (ks * 16 + bColQ) * 2));
                LDSM_X4(bfr[nh * 2][0], bfr[nh * 2][1], bfr[nh * 2 + 1][0], bfr[nh * 2 + 1][1], addr);
            }
#pragma unroll
            for (int mi = 0; mi < 4; mi++) {
                uint32_t a0, a1, a2, a3;
                uint32_t addr = aBase + SWZ128((uint32_t)((aRow0 + mi * 16) * 128 +
                                                          (ks * 16 + aColQ) * 2));
                LDSM_X4(a0, a1, a2, a3, addr);
#pragma unroll
                for (int ni = 0; ni < 4; ni++)
                    MMA_F16(acc[mi][ni], a0, a1, a2, a3, bfr[ni][0], bfr[ni][1]);
            }
        }
    }
    __syncthreads();

    // ---- epilogue ----
    float w = *wp, b = *bp;
    float b2 = fmaf(w, 1e-6f, b);

#pragma unroll
    for (int mi = 0; mi < 4; mi++) {
#pragma unroll
        for (int h = 0; h < 2; h++) {
            int rl = wr * 64 + mi * 16 + (lane >> 2) + 8 * h;
            int grow = rowBase + rl;
            int spk = grow / N_UTT;
            float dg = g_diag[grow];
            float s = 0.f;
#pragma unroll
            for (int ni = 0; ni < 4; ni++) {
                float2 v2 = __half22float2(*(const __half2*)&acc[mi][ni][h]);
#pragma unroll
                for (int e = 0; e < 2; e++) {
                    int col = colBase + wc * 32 + ni * 8 + (lane & 3) * 2 + e;
                    float v = (e == 0) ? v2.x : v2.y;
                    v = (col == spk) ? dg : v;
                    s += __expf(fmaf(w, v, b2));
                }
            }
            s += __shfl_xor_sync(0xffffffffu, s, 1);
            s += __shfl_xor_sync(0xffffffffu, s, 2);
            if ((lane & 3) == 0) rowsum2[rl * 4 + wc] = s;
        }
    }
    __syncthreads();

    if (tid < 128) {
        float v = rowsum2[tid * 4 + 0] + rowsum2[tid * 4 + 1] +
                  rowsum2[tid * 4 + 2] + rowsum2[tid * 4 + 3];
        g_rows[by][bx][tid] = v;
    }
    __threadfence();
    __syncthreads();
    if (tid == 0) s_ord = atomicAdd(&g_cnt[by], 1u);
    __syncthreads();

    if (s_ord == CT - 1) {
        float v = 0.f;
        if (tid < 128) {
            float es = 0.f;
#pragma unroll
            for (int x = 0; x < CT; x++) es += g_rows[by][x][tid];
            float lse = logf(es + 1e-6f);
            float pos = fmaf(w, g_diag[rowBase + tid] + 1e-6f, b);
            v = lse - pos;
        }
        red[tid] = v;
        __syncthreads();
        for (int off = 128; off > 0; off >>= 1) {
            if (tid < off) red[tid] += red[tid + off];
            __syncthreads();
        }
        if (tid == 0) {
            g_part[by] = red[0];
            g_cnt[by] = 0;
            __threadfence();
            unsigned int o = atomicAdd(&g_cnt2, 1u);
            s_last2 = (o == RT - 1) ? 1u : 0u;
        }
        __syncthreads();

        if (s_last2) {
            float s = (tid < RT) ? g_part[tid] : 0.f;
            red[tid] = s;
            __syncthreads();
            for (int off = 128; off > 0; off >>= 1) {
                if (tid < off) red[tid] += red[tid + off];
                __syncthreads();
            }
            if (tid == 0) {
                out[0] = red[0];
                g_cnt2 = 0;
            }
        }
    }
}

// ---------------- launch ----------------
extern "C" void kernel_launch(void* const* d_in, const int* in_sizes, int n_in,
                              void* d_out, int out_size) {
    const float* emb = (const float*)d_in[0];
    const float* w   = (const float*)d_in[1];
    const float* b   = (const float*)d_in[2];
    float* out = (float*)d_out;

    cudaFuncSetAttribute(gemm_loss_kernel,
                         cudaFuncAttributeMaxDynamicSharedMemorySize, SM_TOTAL);

    prep_kernel<<<N_SPK, 256>>>(emb);
    dim3 g2(CT, RT);   // (8, 160)
    gemm_loss_kernel<<<g2, 256, SM_TOTAL>>>(w, b, out);
}